// round 13
// baseline (speedup 1.0000x reference)
#include <cuda_runtime.h>
#include <cuda_bf16.h>

#define BB 2
#define NN 1024
#define DD 16
#define HH 8
#define W1STRIDE (3 * DD + 1)   // 49

typedef unsigned long long ull;

// ---------------------------------------------------------------------------
// Constant pack: only layer-4 weights + small vectors (keeps per-thread LDC
// under the half-rate constant-port floor). W2/W3 go to shared instead.
// ---------------------------------------------------------------------------
struct ConstPack {
    ulonglong2 wd4[HH][HH / 2];     // W4 transposed [h][kp], dup pairs
    ulonglong2 bd[3][HH / 2];       // b2,b3,b4 dup pairs
    ull        w5d[HH];
    ull        w1ad[HH];
    ull        b5d;
};
__constant__ ConstPack c_pack;
__device__   ConstPack g_stage;

__device__ __forceinline__ float tanh_approx(float x) {
    float y;
    asm("tanh.approx.f32 %0, %1;" : "=f"(y) : "f"(x));
    return y;
}
__device__ __forceinline__ ull pack2(float lo, float hi) {
    ull d;
    asm("mov.b64 %0, {%1, %2};" : "=l"(d) : "f"(lo), "f"(hi));
    return d;
}
__device__ __forceinline__ void unpack2(ull v, float& lo, float& hi) {
    asm("mov.b64 {%0, %1}, %2;" : "=f"(lo), "=f"(hi) : "l"(v));
}
__device__ __forceinline__ ull fma2(ull a, ull b, ull c) {
    ull d;
    asm("fma.rn.f32x2 %0, %1, %2, %3;" : "=l"(d) : "l"(a), "l"(b), "l"(c));
    return d;
}
__device__ __forceinline__ ull add2(ull a, ull b) {
    ull d;
    asm("add.rn.f32x2 %0, %1, %2;" : "=l"(d) : "l"(a), "l"(b));
    return d;
}
__device__ __forceinline__ ull tanh2(ull v) {
    float lo, hi;
    unpack2(v, lo, hi);
    return pack2(tanh_approx(lo), tanh_approx(hi));
}

// ---------------------------------------------------------------------------
// Prep kernel: pack W4/bias/w1a/w5 tables into the staging buffer.
// ---------------------------------------------------------------------------
__global__ void pack_kernel(const float* __restrict__ W1,
                            const float* __restrict__ b2,
                            const float* __restrict__ b3,
                            const float* __restrict__ W4, const float* __restrict__ b4,
                            const float* __restrict__ W5, const float* __restrict__ b5) {
    int t = threadIdx.x;
    if (t < 32) {                       // wd4: 8 h x 4 kp
        int h  = t >> 2;
        int kp = t & 3;
        float w0 = W4[(2 * kp)     * HH + h];
        float w1 = W4[(2 * kp + 1) * HH + h];
        g_stage.wd4[h][kp] = make_ulonglong2(pack2(w0, w0), pack2(w1, w1));
    } else if (t < 44) {                // bd: 3 x 4
        int l  = (t - 32) / 4;
        int kp = (t - 32) & 3;
        const float* bb = (l == 0) ? b2 : (l == 1) ? b3 : b4;
        float v0 = bb[2 * kp], v1 = bb[2 * kp + 1];
        g_stage.bd[l][kp] = make_ulonglong2(pack2(v0, v0), pack2(v1, v1));
    } else if (t < 52) {                // w5d
        int h = t - 44;
        float w = W5[h];
        g_stage.w5d[h] = pack2(w, w);
    } else if (t < 60) {                // w1ad
        int h = t - 52;
        float w = W1[h * W1STRIDE + 3 * DD];
        g_stage.w1ad[h] = pack2(w, w);
    } else if (t == 60) {
        float v = b5[0];
        g_stage.b5d = pack2(v, v);
    }
}

// ---------------------------------------------------------------------------
// Main kernel: R11 dataflow (32i x 32j, 4 edges/thread, 2 f32x2 lanes,
// h-outer independent accumulators). Weight traffic SPLIT across pipes:
// W2/W3 dup-pair tables in shared (LDS pipe), W4 + small vectors in
// constant (LDC pipe) — both stay under their respective floors, leaving
// MUFU.TANH as the single binding resource.
// ---------------------------------------------------------------------------
__global__ __launch_bounds__(256, 3)
void edge_mlp_kernel(const float* __restrict__ x,
                     const float* __restrict__ A,
                     const float* __restrict__ vp,
                     const float* __restrict__ W1, const float* __restrict__ b1,
                     const float* __restrict__ W2, const float* __restrict__ W3,
                     float* __restrict__ out) {
    __shared__ __align__(16) float s_xj[32][DD];
    __shared__ __align__(16) float s_xi[32][DD];
    __shared__ __align__(16) float s_w1[HH * W1STRIDE];
    __shared__ __align__(16) float s_tjt[HH][32];   // t_j transposed [h][j]
    __shared__ __align__(16) float s_ti[32 * HH];   // t_i + t_v + b1, [i][h]
    __shared__ __align__(16) ull   s_wd[2][HH * HH]; // W2, W3 transposed [h][k] dup pairs

    const int tid = threadIdx.x;
    const int b  = blockIdx.z;
    const int i0 = blockIdx.y * 32;
    const int j0 = blockIdx.x * 32;

    // --- phase 1: stage x rows + W1 + W2/W3 dup tables into shared ---
    {
        int row = tid >> 2;
        int c4  = (tid & 3) * 4;
        if (row < 32) {
            float4 v = *reinterpret_cast<const float4*>(x + ((size_t)(b * NN + j0 + row)) * DD + c4);
            s_xj[row][c4] = v.x; s_xj[row][c4 + 1] = v.y;
            s_xj[row][c4 + 2] = v.z; s_xj[row][c4 + 3] = v.w;
        } else {
            int r = row - 32;
            float4 v = *reinterpret_cast<const float4*>(x + ((size_t)(b * NN + i0 + r)) * DD + c4);
            s_xi[r][c4] = v.x; s_xi[r][c4 + 1] = v.y;
            s_xi[r][c4 + 2] = v.z; s_xi[r][c4 + 3] = v.w;
        }
        s_w1[tid] = W1[tid];
        if (tid < HH * W1STRIDE - 256) s_w1[256 + tid] = W1[256 + tid];
        if (tid < 64) {
            int dstT = (tid & 7) * HH + (tid >> 3);   // [k][h] -> [h][k]
            float w2 = W2[tid], w3 = W3[tid];
            s_wd[0][dstT] = pack2(w2, w2);
            s_wd[1][dstT] = pack2(w3, w3);
        }
    }
    __syncthreads();

    const int ii = tid >> 3;         // 0..31
    const int jl = (tid & 7) * 4;    // 0,4,...,28

    // Early global A load to overlap with phase 2
    const size_t off = ((size_t)(b * NN + i0 + ii)) * NN + j0 + jl;
    float4 a4 = *reinterpret_cast<const float4*>(A + off);

    // --- phase 2: per-row projections ---
    {
        int n = tid >> 3;
        int h = tid & 7;
        const float* wr = s_w1 + h * W1STRIDE;
        float tj = 0.0f, ti = 0.0f;
#pragma unroll
        for (int c = 0; c < DD; c++) {
            tj += s_xj[n][c] * wr[c];
            ti += s_xi[n][c] * wr[DD + c];
        }
        float tv = b1[h];
#pragma unroll
        for (int c = 0; c < DD; c++)
            tv += vp[b * DD + c] * wr[2 * DD + c];
        s_tjt[h][n] = tj;
        s_ti[n * HH + h] = ti + tv;
    }
    __syncthreads();

    // --- phase 3: packed edge MLP ---
    ull a2lo = pack2(a4.x, a4.y);
    ull a2hi = pack2(a4.z, a4.w);

    // layer 1 (w1a from constant)
    ull h2[2][HH];
#pragma unroll
    for (int h = 0; h < HH; h++) {
        float4 tj4 = *reinterpret_cast<const float4*>(&s_tjt[h][jl]);
        float tival = s_ti[ii * HH + h];
        ull tiv = pack2(tival, tival);
        ull wa = c_pack.w1ad[h];
        h2[0][h] = tanh2(fma2(a2lo, wa, add2(pack2(tj4.x, tj4.y), tiv)));
        h2[1][h] = tanh2(fma2(a2hi, wa, add2(pack2(tj4.z, tj4.w), tiv)));
    }

    // layers 2..4: W2/W3 from shared, W4 from constant
#pragma unroll
    for (int l = 0; l < 3; l++) {
        ull acc[2][HH];
#pragma unroll
        for (int kp = 0; kp < HH / 2; kp++) {
            ulonglong2 bk = c_pack.bd[l][kp];
            acc[0][kp * 2] = bk.x; acc[1][kp * 2] = bk.x;
            acc[0][kp * 2 + 1] = bk.y; acc[1][kp * 2 + 1] = bk.y;
        }
#pragma unroll
        for (int h = 0; h < HH; h++) {
            ull hv0 = h2[0][h];
            ull hv1 = h2[1][h];
#pragma unroll
            for (int kp = 0; kp < HH / 2; kp++) {
                ulonglong2 w = (l < 2)
                    ? *reinterpret_cast<const ulonglong2*>(&s_wd[l][h * HH + kp * 2])
                    : c_pack.wd4[h][kp];
                acc[0][kp * 2]     = fma2(hv0, w.x, acc[0][kp * 2]);
                acc[1][kp * 2]     = fma2(hv1, w.x, acc[1][kp * 2]);
                acc[0][kp * 2 + 1] = fma2(hv0, w.y, acc[0][kp * 2 + 1]);
                acc[1][kp * 2 + 1] = fma2(hv1, w.y, acc[1][kp * 2 + 1]);
            }
        }
#pragma unroll
        for (int p = 0; p < 2; p++)
#pragma unroll
            for (int k = 0; k < HH; k++)
                h2[p][k] = tanh2(acc[p][k]);
    }

    // output layer (constant)
    ull o2lo = c_pack.b5d, o2hi = c_pack.b5d;
#pragma unroll
    for (int h = 0; h < HH; h++) {
        ull w = c_pack.w5d[h];
        o2lo = fma2(h2[0][h], w, o2lo);
        o2hi = fma2(h2[1][h], w, o2hi);
    }
    float4 o4;
    unpack2(o2lo, o4.x, o4.y);
    unpack2(o2hi, o4.z, o4.w);
    *reinterpret_cast<float4*>(out + off) = o4;
}

// ---------------------------------------------------------------------------
extern "C" void kernel_launch(void* const* d_in, const int* in_sizes, int n_in,
                              void* d_out, int out_size) {
    const float* x  = (const float*)d_in[0];
    const float* A  = (const float*)d_in[1];
    const float* vp = (const float*)d_in[2];
    const float* W1 = (const float*)d_in[3];
    const float* b1 = (const float*)d_in[4];
    const float* W2 = (const float*)d_in[5];
    const float* b2 = (const float*)d_in[6];
    const float* W3 = (const float*)d_in[7];
    const float* b3 = (const float*)d_in[8];
    const float* W4 = (const float*)d_in[9];
    const float* b4 = (const float*)d_in[10];
    const float* W5 = (const float*)d_in[11];
    const float* b5 = (const float*)d_in[12];
    float* out = (float*)d_out;

    // 1) pack constant tables into the staging buffer
    pack_kernel<<<1, 64>>>(W1, b2, b3, W4, b4, W5, b5);

    // 2) staging -> __constant__ (capture-safe D2D memcpy)
    void* stage_ptr = nullptr;
    void* const_ptr = nullptr;
    cudaGetSymbolAddress(&stage_ptr, g_stage);
    cudaGetSymbolAddress(&const_ptr, c_pack);
    cudaMemcpyAsync(const_ptr, stage_ptr, sizeof(ConstPack),
                    cudaMemcpyDeviceToDevice, 0);

    // 3) main kernel
    dim3 grid(NN / 32, NN / 32, BB);   // 32 x 32 x 2 = 2048 blocks
    edge_mlp_kernel<<<grid, 256>>>(x, A, vp, W1, b1, W2, W3, out);
}

// round 15
// speedup vs baseline: 1.1209x; 1.1209x over previous
#include <cuda_runtime.h>
#include <cuda_bf16.h>

#define BB 2
#define NN 1024
#define DD 16
#define HH 8
#define W1STRIDE (3 * DD + 1)   // 49

typedef unsigned long long ull;

// ---------------------------------------------------------------------------
// Constant-memory weight pack (R11 layout: all uniform weights in constant).
// ---------------------------------------------------------------------------
struct ConstPack {
    ulonglong2 wd[3][HH][HH / 2];   // [l][h][kp]: dup pairs of W[2kp][h], W[2kp+1][h]
    ulonglong2 bd[3][HH / 2];
    ull        w5d[HH];
    ull        w1ad[HH];
    ull        b5d;
};
__constant__ ConstPack c_pack;
__device__   ConstPack g_stage;

// Precomputed per-row projections (device globals; 32 KB each)
__device__ float g_tj [BB * HH * NN];   // [b][h][n]  (transposed for float4-j reads)
__device__ float g_tiv[BB * NN * HH];   // [b][n][h]  (t_i + t_v + b1)

__device__ __forceinline__ float tanh_approx(float x) {
    float y;
    asm("tanh.approx.f32 %0, %1;" : "=f"(y) : "f"(x));
    return y;
}
__device__ __forceinline__ ull pack2(float lo, float hi) {
    ull d;
    asm("mov.b64 %0, {%1, %2};" : "=l"(d) : "f"(lo), "f"(hi));
    return d;
}
__device__ __forceinline__ void unpack2(ull v, float& lo, float& hi) {
    asm("mov.b64 {%0, %1}, %2;" : "=f"(lo), "=f"(hi) : "l"(v));
}
__device__ __forceinline__ ull fma2(ull a, ull b, ull c) {
    ull d;
    asm("fma.rn.f32x2 %0, %1, %2, %3;" : "=l"(d) : "l"(a), "l"(b), "l"(c));
    return d;
}
__device__ __forceinline__ ull add2(ull a, ull b) {
    ull d;
    asm("add.rn.f32x2 %0, %1, %2;" : "=l"(d) : "l"(a), "l"(b));
    return d;
}
__device__ __forceinline__ ull tanh2(ull v) {
    float lo, hi;
    unpack2(v, lo, hi);
    return pack2(tanh_approx(lo), tanh_approx(hi));
}

// ---------------------------------------------------------------------------
// Pack kernel (identical structure to the R11-proven version).
// ---------------------------------------------------------------------------
__global__ void pack_kernel(const float* __restrict__ W1,
                            const float* __restrict__ W2, const float* __restrict__ b2,
                            const float* __restrict__ W3, const float* __restrict__ b3,
                            const float* __restrict__ W4, const float* __restrict__ b4,
                            const float* __restrict__ W5, const float* __restrict__ b5) {
    int t = threadIdx.x;
    if (t < 96) {                       // wd: 3 x 8 x 4
        int l  = t / 32;
        int h  = (t / 4) & 7;
        int kp = t & 3;
        const float* W = (l == 0) ? W2 : (l == 1) ? W3 : W4;
        float w0 = W[(2 * kp)     * HH + h];
        float w1 = W[(2 * kp + 1) * HH + h];
        g_stage.wd[l][h][kp] = make_ulonglong2(pack2(w0, w0), pack2(w1, w1));
    } else if (t < 108) {               // bd: 3 x 4
        int l  = (t - 96) / 4;
        int kp = (t - 96) & 3;
        const float* bb = (l == 0) ? b2 : (l == 1) ? b3 : b4;
        float v0 = bb[2 * kp], v1 = bb[2 * kp + 1];
        g_stage.bd[l][kp] = make_ulonglong2(pack2(v0, v0), pack2(v1, v1));
    } else if (t < 116) {               // w5d
        int h = t - 108;
        float w = W5[h];
        g_stage.w5d[h] = pack2(w, w);
    } else if (t < 124) {               // w1ad
        int h = t - 116;
        float w = W1[h * W1STRIDE + 3 * DD];
        g_stage.w1ad[h] = pack2(w, w);
    } else if (t == 124) {
        float v = b5[0];
        g_stage.b5d = pack2(v, v);
    }
}

// ---------------------------------------------------------------------------
// Projection kernel: t_j (transposed) and t_i + t_v + b1 for all (b, n, h).
// 64 blocks x 256 threads; one (b, n, h) triple per thread.
// ---------------------------------------------------------------------------
__global__ void proj_kernel(const float* __restrict__ x,
                            const float* __restrict__ vp,
                            const float* __restrict__ W1,
                            const float* __restrict__ b1) {
    int idx = blockIdx.x * 256 + threadIdx.x;   // 0 .. 16383
    int b = idx >> 13;
    int n = (idx >> 3) & (NN - 1);
    int h = idx & 7;
    const float* wr = W1 + h * W1STRIDE;
    const float* xr = x + ((size_t)(b * NN + n)) * DD;
    float tj = 0.0f, ti = 0.0f, tv = b1[h];
#pragma unroll
    for (int c = 0; c < DD; c++) {
        tj += xr[c] * wr[c];
        ti += xr[c] * wr[DD + c];
        tv += vp[b * DD + c] * wr[2 * DD + c];
    }
    g_tj [(b * HH + h) * NN + n] = tj;
    g_tiv[(b * NN + n) * HH + h] = ti + tv;
}

// ---------------------------------------------------------------------------
// Main kernel: NO shared memory, NO barriers. 32i x 32j tile, 4 edges/thread
// as 2 f32x2 lanes; projections streamed from global (LDG.128, L2-cached),
// weights from constant. Pure FFMA2 + MUFU.TANH stream.
// ---------------------------------------------------------------------------
__global__ __launch_bounds__(256, 3)
void edge_mlp_kernel(const float* __restrict__ A, float* __restrict__ out) {
    const int tid = threadIdx.x;
    const int b  = blockIdx.z;
    const int i0 = blockIdx.y * 32;
    const int j0 = blockIdx.x * 32;
    const int ii = tid >> 3;         // 0..31
    const int jl = (tid & 7) * 4;    // 0,4,...,28

    const size_t off = ((size_t)(b * NN + i0 + ii)) * NN + j0 + jl;
    float4 a4 = *reinterpret_cast<const float4*>(A + off);

    // tiv row (8 floats) via two LDG.128
    const float4* tivp = reinterpret_cast<const float4*>(&g_tiv[((size_t)(b * NN + i0 + ii)) * HH]);
    float4 ti03 = tivp[0];
    float4 ti47 = tivp[1];
    float tiv[HH] = { ti03.x, ti03.y, ti03.z, ti03.w,
                      ti47.x, ti47.y, ti47.z, ti47.w };

    ull a2lo = pack2(a4.x, a4.y);
    ull a2hi = pack2(a4.z, a4.w);

    // layer 1: t_j via transposed global reads (one float4 per h)
    ull h2[2][HH];
#pragma unroll
    for (int h = 0; h < HH; h++) {
        float4 tj4 = *reinterpret_cast<const float4*>(&g_tj[(b * HH + h) * NN + j0 + jl]);
        ull tivd = pack2(tiv[h], tiv[h]);
        ull wa = c_pack.w1ad[h];
        h2[0][h] = tanh2(fma2(a2lo, wa, add2(pack2(tj4.x, tj4.y), tivd)));
        h2[1][h] = tanh2(fma2(a2hi, wa, add2(pack2(tj4.z, tj4.w), tivd)));
    }

    // layers 2..4: h outer, k inner; 16 independent acc chains, constant weights
#pragma unroll
    for (int l = 0; l < 3; l++) {
        ull acc[2][HH];
#pragma unroll
        for (int kp = 0; kp < HH / 2; kp++) {
            ulonglong2 bk = c_pack.bd[l][kp];
            acc[0][kp * 2] = bk.x; acc[1][kp * 2] = bk.x;
            acc[0][kp * 2 + 1] = bk.y; acc[1][kp * 2 + 1] = bk.y;
        }
#pragma unroll
        for (int h = 0; h < HH; h++) {
            ull hv0 = h2[0][h];
            ull hv1 = h2[1][h];
#pragma unroll
            for (int kp = 0; kp < HH / 2; kp++) {
                ulonglong2 w = c_pack.wd[l][h][kp];
                acc[0][kp * 2]     = fma2(hv0, w.x, acc[0][kp * 2]);
                acc[1][kp * 2]     = fma2(hv1, w.x, acc[1][kp * 2]);
                acc[0][kp * 2 + 1] = fma2(hv0, w.y, acc[0][kp * 2 + 1]);
                acc[1][kp * 2 + 1] = fma2(hv1, w.y, acc[1][kp * 2 + 1]);
            }
        }
#pragma unroll
        for (int p = 0; p < 2; p++)
#pragma unroll
            for (int k = 0; k < HH; k++)
                h2[p][k] = tanh2(acc[p][k]);
    }

    // output layer
    ull o2lo = c_pack.b5d, o2hi = c_pack.b5d;
#pragma unroll
    for (int h = 0; h < HH; h++) {
        ull w = c_pack.w5d[h];
        o2lo = fma2(h2[0][h], w, o2lo);
        o2hi = fma2(h2[1][h], w, o2hi);
    }
    float4 o4;
    unpack2(o2lo, o4.x, o4.y);
    unpack2(o2hi, o4.z, o4.w);
    *reinterpret_cast<float4*>(out + off) = o4;
}

// ---------------------------------------------------------------------------
extern "C" void kernel_launch(void* const* d_in, const int* in_sizes, int n_in,
                              void* d_out, int out_size) {
    const float* x  = (const float*)d_in[0];
    const float* A  = (const float*)d_in[1];
    const float* vp = (const float*)d_in[2];
    const float* W1 = (const float*)d_in[3];
    const float* b1 = (const float*)d_in[4];
    const float* W2 = (const float*)d_in[5];
    const float* b2 = (const float*)d_in[6];
    const float* W3 = (const float*)d_in[7];
    const float* b3 = (const float*)d_in[8];
    const float* W4 = (const float*)d_in[9];
    const float* b4 = (const float*)d_in[10];
    const float* W5 = (const float*)d_in[11];
    const float* b5 = (const float*)d_in[12];
    float* out = (float*)d_out;

    // 1) constant staging (R11-proven) + projections
    pack_kernel<<<1, 128>>>(W1, W2, b2, W3, b3, W4, b4, W5, b5);
    proj_kernel<<<64, 256>>>(x, vp, W1, b1);

    // 2) staging -> __constant__ (capture-safe D2D memcpy)
    void* stage_ptr = nullptr;
    void* const_ptr = nullptr;
    cudaGetSymbolAddress(&stage_ptr, g_stage);
    cudaGetSymbolAddress(&const_ptr, c_pack);
    cudaMemcpyAsync(const_ptr, stage_ptr, sizeof(ConstPack),
                    cudaMemcpyDeviceToDevice, 0);

    // 3) main kernel (no smem, no barriers)
    dim3 grid(NN / 32, NN / 32, BB);   // 32 x 32 x 2 = 2048 blocks
    edge_mlp_kernel<<<grid, 256>>>(A, out);
}

// round 16
// speedup vs baseline: 1.1552x; 1.0306x over previous
#include <cuda_runtime.h>
#include <cuda_bf16.h>

#define BB 2
#define NN 1024
#define DD 16
#define HH 8
#define W1STRIDE (3 * DD + 1)   // 49

typedef unsigned long long ull;

// ---------------------------------------------------------------------------
// Constant-memory weight pack (all uniform weights in constant).
// ---------------------------------------------------------------------------
struct ConstPack {
    ulonglong2 wd[3][HH][HH / 2];   // [l][h][kp]: dup pairs of W[2kp][h], W[2kp+1][h]
    ulonglong2 bd[3][HH / 2];
    ull        w5d[HH];
    ull        w1ad[HH];
    ull        b5d;
};
__constant__ ConstPack c_pack;
__device__   ConstPack g_stage;

// Precomputed per-row projections (device globals; 32 KB each)
__device__ float g_tj [BB * HH * NN];   // [b][h][n]  (transposed for float4-j reads)
__device__ float g_tiv[BB * NN * HH];   // [b][n][h]  (t_i + t_v + b1)

__device__ __forceinline__ float tanh_approx(float x) {
    float y;
    asm("tanh.approx.f32 %0, %1;" : "=f"(y) : "f"(x));
    return y;
}
__device__ __forceinline__ ull pack2(float lo, float hi) {
    ull d;
    asm("mov.b64 %0, {%1, %2};" : "=l"(d) : "f"(lo), "f"(hi));
    return d;
}
__device__ __forceinline__ void unpack2(ull v, float& lo, float& hi) {
    asm("mov.b64 {%0, %1}, %2;" : "=f"(lo), "=f"(hi) : "l"(v));
}
__device__ __forceinline__ ull fma2(ull a, ull b, ull c) {
    ull d;
    asm("fma.rn.f32x2 %0, %1, %2, %3;" : "=l"(d) : "l"(a), "l"(b), "l"(c));
    return d;
}
__device__ __forceinline__ ull add2(ull a, ull b) {
    ull d;
    asm("add.rn.f32x2 %0, %1, %2;" : "=l"(d) : "l"(a), "l"(b));
    return d;
}
__device__ __forceinline__ ull tanh2(ull v) {
    float lo, hi;
    unpack2(v, lo, hi);
    return pack2(tanh_approx(lo), tanh_approx(hi));
}

// ---------------------------------------------------------------------------
// Merged prep kernel: 64 blocks x 256 threads.
// All blocks: per-row projections (one (b, n, h) triple per thread).
// Block 0 additionally stages the constant pack (parallel with other blocks).
// ---------------------------------------------------------------------------
__global__ void prep_kernel(const float* __restrict__ x,
                            const float* __restrict__ vp,
                            const float* __restrict__ W1, const float* __restrict__ b1,
                            const float* __restrict__ W2, const float* __restrict__ b2,
                            const float* __restrict__ W3, const float* __restrict__ b3,
                            const float* __restrict__ W4, const float* __restrict__ b4,
                            const float* __restrict__ W5, const float* __restrict__ b5) {
    int idx = blockIdx.x * 256 + threadIdx.x;   // 0 .. 16383
    int b = idx >> 13;
    int n = (idx >> 3) & (NN - 1);
    int h = idx & 7;
    const float* wr = W1 + h * W1STRIDE;
    const float* xr = x + ((size_t)(b * NN + n)) * DD;
    float tj = 0.0f, ti = 0.0f, tv = b1[h];
#pragma unroll
    for (int c = 0; c < DD; c++) {
        tj += xr[c] * wr[c];
        ti += xr[c] * wr[DD + c];
        tv += vp[b * DD + c] * wr[2 * DD + c];
    }
    g_tj [(b * HH + h) * NN + n] = tj;
    g_tiv[(b * NN + n) * HH + h] = ti + tv;

    if (blockIdx.x == 0) {
        int t = threadIdx.x;
        if (t < 96) {                       // wd: 3 x 8 x 4
            int l  = t / 32;
            int hh = (t / 4) & 7;
            int kp = t & 3;
            const float* W = (l == 0) ? W2 : (l == 1) ? W3 : W4;
            float w0 = W[(2 * kp)     * HH + hh];
            float w1 = W[(2 * kp + 1) * HH + hh];
            g_stage.wd[l][hh][kp] = make_ulonglong2(pack2(w0, w0), pack2(w1, w1));
        } else if (t < 108) {               // bd: 3 x 4
            int l  = (t - 96) / 4;
            int kp = (t - 96) & 3;
            const float* bb = (l == 0) ? b2 : (l == 1) ? b3 : b4;
            float v0 = bb[2 * kp], v1 = bb[2 * kp + 1];
            g_stage.bd[l][kp] = make_ulonglong2(pack2(v0, v0), pack2(v1, v1));
        } else if (t < 116) {               // w5d
            int hh = t - 108;
            float w = W5[hh];
            g_stage.w5d[hh] = pack2(w, w);
        } else if (t < 124) {               // w1ad
            int hh = t - 116;
            float w = W1[hh * W1STRIDE + 3 * DD];
            g_stage.w1ad[hh] = pack2(w, w);
        } else if (t == 124) {
            float v = b5[0];
            g_stage.b5d = pack2(v, v);
        }
    }
}

// ---------------------------------------------------------------------------
// Main kernel: NO shared memory, NO barriers. 32i x 32j tile, 4 edges/thread
// as 2 f32x2 lanes; projections streamed from global (LDG.128, L2-cached),
// weights from constant. Pure FFMA2 + MUFU.TANH stream.
// ---------------------------------------------------------------------------
__global__ __launch_bounds__(256, 3)
void edge_mlp_kernel(const float* __restrict__ A, float* __restrict__ out) {
    const int tid = threadIdx.x;
    const int b  = blockIdx.z;
    const int i0 = blockIdx.y * 32;
    const int j0 = blockIdx.x * 32;
    const int ii = tid >> 3;         // 0..31
    const int jl = (tid & 7) * 4;    // 0,4,...,28

    const size_t off = ((size_t)(b * NN + i0 + ii)) * NN + j0 + jl;
    float4 a4 = *reinterpret_cast<const float4*>(A + off);

    // tiv row (8 floats) via two LDG.128
    const float4* tivp = reinterpret_cast<const float4*>(&g_tiv[((size_t)(b * NN + i0 + ii)) * HH]);
    float4 ti03 = tivp[0];
    float4 ti47 = tivp[1];
    float tiv[HH] = { ti03.x, ti03.y, ti03.z, ti03.w,
                      ti47.x, ti47.y, ti47.z, ti47.w };

    ull a2lo = pack2(a4.x, a4.y);
    ull a2hi = pack2(a4.z, a4.w);

    // layer 1: t_j via transposed global reads (one float4 per h)
    ull h2[2][HH];
#pragma unroll
    for (int h = 0; h < HH; h++) {
        float4 tj4 = *reinterpret_cast<const float4*>(&g_tj[(b * HH + h) * NN + j0 + jl]);
        ull tivd = pack2(tiv[h], tiv[h]);
        ull wa = c_pack.w1ad[h];
        h2[0][h] = tanh2(fma2(a2lo, wa, add2(pack2(tj4.x, tj4.y), tivd)));
        h2[1][h] = tanh2(fma2(a2hi, wa, add2(pack2(tj4.z, tj4.w), tivd)));
    }

    // layers 2..4: h outer, k inner; 16 independent acc chains, constant weights
#pragma unroll
    for (int l = 0; l < 3; l++) {
        ull acc[2][HH];
#pragma unroll
        for (int kp = 0; kp < HH / 2; kp++) {
            ulonglong2 bk = c_pack.bd[l][kp];
            acc[0][kp * 2] = bk.x; acc[1][kp * 2] = bk.x;
            acc[0][kp * 2 + 1] = bk.y; acc[1][kp * 2 + 1] = bk.y;
        }
#pragma unroll
        for (int h = 0; h < HH; h++) {
            ull hv0 = h2[0][h];
            ull hv1 = h2[1][h];
#pragma unroll
            for (int kp = 0; kp < HH / 2; kp++) {
                ulonglong2 w = c_pack.wd[l][h][kp];
                acc[0][kp * 2]     = fma2(hv0, w.x, acc[0][kp * 2]);
                acc[1][kp * 2]     = fma2(hv1, w.x, acc[1][kp * 2]);
                acc[0][kp * 2 + 1] = fma2(hv0, w.y, acc[0][kp * 2 + 1]);
                acc[1][kp * 2 + 1] = fma2(hv1, w.y, acc[1][kp * 2 + 1]);
            }
        }
#pragma unroll
        for (int p = 0; p < 2; p++)
#pragma unroll
            for (int k = 0; k < HH; k++)
                h2[p][k] = tanh2(acc[p][k]);
    }

    // output layer
    ull o2lo = c_pack.b5d, o2hi = c_pack.b5d;
#pragma unroll
    for (int h = 0; h < HH; h++) {
        ull w = c_pack.w5d[h];
        o2lo = fma2(h2[0][h], w, o2lo);
        o2hi = fma2(h2[1][h], w, o2hi);
    }
    float4 o4;
    unpack2(o2lo, o4.x, o4.y);
    unpack2(o2hi, o4.z, o4.w);
    *reinterpret_cast<float4*>(out + off) = o4;
}

// ---------------------------------------------------------------------------
extern "C" void kernel_launch(void* const* d_in, const int* in_sizes, int n_in,
                              void* d_out, int out_size) {
    const float* x  = (const float*)d_in[0];
    const float* A  = (const float*)d_in[1];
    const float* vp = (const float*)d_in[2];
    const float* W1 = (const float*)d_in[3];
    const float* b1 = (const float*)d_in[4];
    const float* W2 = (const float*)d_in[5];
    const float* b2 = (const float*)d_in[6];
    const float* W3 = (const float*)d_in[7];
    const float* b3 = (const float*)d_in[8];
    const float* W4 = (const float*)d_in[9];
    const float* b4 = (const float*)d_in[10];
    const float* W5 = (const float*)d_in[11];
    const float* b5 = (const float*)d_in[12];
    float* out = (float*)d_out;

    // 1) single merged prelude: projections + constant staging
    prep_kernel<<<64, 256>>>(x, vp, W1, b1, W2, b2, W3, b3, W4, b4, W5, b5);

    // 2) staging -> __constant__ (capture-safe D2D memcpy)
    void* stage_ptr = nullptr;
    void* const_ptr = nullptr;
    cudaGetSymbolAddress(&stage_ptr, g_stage);
    cudaGetSymbolAddress(&const_ptr, c_pack);
    cudaMemcpyAsync(const_ptr, stage_ptr, sizeof(ConstPack),
                    cudaMemcpyDeviceToDevice, 0);

    // 3) main kernel (no smem, no barriers)
    dim3 grid(NN / 32, NN / 32, BB);   // 32 x 32 x 2 = 2048 blocks
    edge_mlp_kernel<<<grid, 256>>>(A, out);
}